// round 3
// baseline (speedup 1.0000x reference)
#include <cuda_runtime.h>
#include <stdint.h>

// Capacity sized for the 4096x4096 problem (16,777,216 elements).
#define MAX_ELEMS   (1u << 24)
#define MAX_BLOCKS  (MAX_ELEMS / 64)

__device__ unsigned g_smin_bits;
__device__ unsigned g_smax_bits;
__device__ float    g_scales[MAX_BLOCKS];         // raw per-block scales (1 MB)
__device__ float    g_dscales[MAX_BLOCKS];        // double-quantized scales (1 MB)
__device__ unsigned char g_codes[MAX_ELEMS / 2];  // 4-bit codes, 2/byte (8 MB)

__global__ void k_init() {
    g_smin_bits = 0x7F800000u;  // +inf
    g_smax_bits = 0u;
}

// Swizzled per-warp smem address (float index) for element `pos` (0..63) of
// local block `b` (0..31). XOR at float4 granularity -> LDS.128/STS.128
// conflict-free both directions.
__device__ __forceinline__ int sw_addr(int b, int pos) {
    return (b << 6) + (((pos & ~3) ^ ((b & 15) << 2)) | (pos & 3));
}

// Kernel 1: per FP4-block (64 elems) percentile scale + 4-bit code pack.
// CTA = 128 threads = 4 warps. One warp handles 32 blocks (8KB), loaded
// coalesced into a per-warp smem tile; one THREAD then owns one block.
__global__ __launch_bounds__(128) void k_quant(const float* __restrict__ x,
                                               int nblocks, int n) {
    __shared__ float sm[4][2048];   // 4 warps x 8KB

    const int w = threadIdx.x >> 5;
    const int l = threadIdx.x & 31;
    const int warp_blk0 = blockIdx.x * 128 + w * 32;  // first FP4 block of this warp
    const int blk = warp_blk0 + l;                    // this thread's FP4 block
    const bool active = blk < nblocks;
    const long warp_e0 = (long)warp_blk0 * 64;

    float* smw = sm[w];
    bool fast = (warp_blk0 + 32 <= nblocks) && (warp_e0 + 2048 <= (long)n);

    if (fast) {
        // Coalesced: lane l, iter i loads float4 #(i*32+l) of the warp tile.
        const float4* p = reinterpret_cast<const float4*>(x + warp_e0);
        float4* s4 = reinterpret_cast<float4*>(smw);
        #pragma unroll
        for (int i = 0; i < 16; i++) {
            float4 f = p[i * 32 + l];
            int e = i * 128 + 4 * l;        // element offset within warp tile
            s4[sw_addr(e >> 6, e & 63) >> 2] = f;
        }
    } else if (active) {
        // Tail: direct bounded gather into own region (no cross-lane sharing).
        int base = blk * 64;
        for (int i = 0; i < 64; i++) {
            float v = (base + i < n) ? x[base + i] : 0.0f;
            smw[sw_addr(l, i)] = v;
        }
    }
    __syncwarp();

    float scale = 0.0f;
    if (active) {
        const float4* s4 = reinterpret_cast<const float4*>(smw);

        // Pass 1: branchless top-5 of |v|: m1 >= m2 >= m3 >= m4 >= m5
        float m1 = -1.f, m2 = -1.f, m3 = -1.f, m4 = -1.f, m5 = -1.f;
        #pragma unroll
        for (int i = 0; i < 16; i++) {
            float4 f = s4[sw_addr(l, 4 * i) >> 2];
            float q[4] = {f.x, f.y, f.z, f.w};
            #pragma unroll
            for (int u = 0; u < 4; u++) {
                float t = fabsf(q[u]), h;
                h = fmaxf(m1, t); t = fminf(m1, t); m1 = h;
                h = fmaxf(m2, t); t = fminf(m2, t); m2 = h;
                h = fmaxf(m3, t); t = fminf(m3, t); m3 = h;
                h = fmaxf(m4, t); t = fminf(m4, t); m4 = h;
                m5 = fmaxf(m5, t);
            }
        }
        // 95th pct of 64 vals: sorted[59] + 0.85*(sorted[60]-sorted[59])
        scale = fmaxf(m5 + 0.85f * (m4 - m5), 1e-8f);
        g_scales[blk] = scale;

        // Pass 2: quantize via midpoint thresholds (scale > 0).
        // k = magnitude rank 0..5 -> level {0,.75,1,1.5,2,3}; code=(sign<<3)|k
        float t1 = 0.375f * scale, t2 = 0.875f * scale, t3 = 1.25f * scale,
              t4 = 1.75f  * scale, t5 = 2.5f  * scale;
        unsigned pk[8];
        #pragma unroll
        for (int j = 0; j < 8; j++) {
            unsigned word = 0;
            #pragma unroll
            for (int half = 0; half < 2; half++) {
                float4 f = s4[sw_addr(l, 8 * j + 4 * half) >> 2];
                float q[4] = {f.x, f.y, f.z, f.w};
                #pragma unroll
                for (int u = 0; u < 4; u++) {
                    float a = fabsf(q[u]);
                    unsigned k = (unsigned)(a > t1) + (unsigned)(a > t2) +
                                 (unsigned)(a > t3) + (unsigned)(a > t4) +
                                 (unsigned)(a > t5);
                    unsigned c = ((__float_as_uint(q[u]) >> 31) << 3) | k;
                    word |= c << (4 * (half * 4 + u));
                }
            }
            pk[j] = word;
        }
        uint4* dst = reinterpret_cast<uint4*>(g_codes + (size_t)blk * 32);
        dst[0] = make_uint4(pk[0], pk[1], pk[2], pk[3]);
        dst[1] = make_uint4(pk[4], pk[5], pk[6], pk[7]);
    }

    // CTA reduce of scale min/max -> 2 atomics per CTA
    float smin = active ? scale : __int_as_float(0x7F800000);
    float smax = active ? scale : 0.0f;
    #pragma unroll
    for (int off = 16; off; off >>= 1) {
        smin = fminf(smin, __shfl_xor_sync(0xFFFFFFFFu, smin, off));
        smax = fmaxf(smax, __shfl_xor_sync(0xFFFFFFFFu, smax, off));
    }
    __shared__ float sm_min[4], sm_max[4];
    if (l == 0) { sm_min[w] = smin; sm_max[w] = smax; }
    __syncthreads();
    if (threadIdx.x == 0) {
        float mn = sm_min[0], mx = sm_max[0];
        #pragma unroll
        for (int i = 1; i < 4; i++) { mn = fminf(mn, sm_min[i]); mx = fmaxf(mx, sm_max[i]); }
        atomicMin(&g_smin_bits, __float_as_uint(mn));  // scales > 0: uint order == float order
        atomicMax(&g_smax_bits, __float_as_uint(mx));
    }
}

// Kernel 2: double-quantize scales once (drops scale_min, faithful to source).
__global__ __launch_bounds__(256) void k_dscale(int nblocks) {
    int b = blockIdx.x * 256 + threadIdx.x;
    if (b >= nblocks) return;
    float mn = __uint_as_float(g_smin_bits);
    float mx = __uint_as_float(g_smax_bits);
    float s = g_scales[b];
    float ds;
    if (mx > mn) {
        float ss = __fdiv_rn(mx - mn, 255.0f);
        float q = rintf(__fdiv_rn(s - mn, ss));   // jnp.round == half-even == rintf
        q = fminf(fmaxf(q, 0.0f), 255.0f);
        ds = q * ss;
    } else {
        ds = 0.0f;  // q_scales = 0 when smax == smin
    }
    g_dscales[b] = ds;
}

// Kernel 3: decode codes, multiply by dequantized scale. 8 elems/thread:
// codes read = 1 coalesced uint/thread; out = 2 complementary STG.128
// patterns (minimum wavefronts).
__global__ __launch_bounds__(256) void k_dequant(float* __restrict__ out, int n) {
    int t = blockIdx.x * 256 + threadIdx.x;
    int e = t * 8;
    if (e >= n) return;

    float ds = g_dscales[e >> 6];
    unsigned w = *reinterpret_cast<const unsigned*>(g_codes + (e >> 1));

    float r[8];
    #pragma unroll
    for (int i = 0; i < 8; i++) {
        unsigned c = (w >> (4 * i)) & 15u;
        unsigned k = c & 7u;
        // decode level: mant = (k&1)?1.5:1.0, exp = (k>>1)-1 -> {.75,1,1.5,2,3}
        unsigned bits = ((c & 8u) << 28) | ((126u + (k >> 1)) << 23) | ((k & 1u) << 22);
        r[i] = k ? __uint_as_float(bits) * ds : 0.0f;
    }

    if (e + 8 <= n) {
        float4* o = reinterpret_cast<float4*>(out + e);
        o[0] = make_float4(r[0], r[1], r[2], r[3]);
        o[1] = make_float4(r[4], r[5], r[6], r[7]);
    } else {
        for (int i = 0; i < 8 && e + i < n; i++) out[e + i] = r[i];
    }
}

extern "C" void kernel_launch(void* const* d_in, const int* in_sizes, int n_in,
                              void* d_out, int out_size) {
    const float* x = (const float*)d_in[0];
    float* out = (float*)d_out;
    int n = in_sizes[0];
    int nblocks = (n + 63) / 64;

    k_init<<<1, 1>>>();
    k_quant<<<(nblocks + 127) / 128, 128>>>(x, nblocks, n);
    k_dscale<<<(nblocks + 255) / 256, 256>>>(nblocks);
    int nthreads2 = (n + 7) / 8;
    k_dequant<<<(nthreads2 + 255) / 256, 256>>>(out, n);
}